// round 12
// baseline (speedup 1.0000x reference)
#include <cuda_runtime.h>
#include <cuda_bf16.h>
#include <cstdint>

#define NMAX 20000
#define EMAX 400000
#define DF   512

// ---------------- scratch (static device globals; no allocs) ----------------
__device__ float g_bufA[(size_t)NMAX * DF];        // fp32 hs / logits
__device__ __nv_bfloat16 g_ah[(size_t)NMAX * DF];  // activation hi
__device__ __nv_bfloat16 g_al[(size_t)NMAX * DF];  // activation lo
__device__ __nv_bfloat16 g_bh[(size_t)NMAX * DF];  // fc1-out hi
__device__ __nv_bfloat16 g_bl[(size_t)NMAX * DF];  // fc1-out lo
__device__ __nv_bfloat16 g_wh[3 * 512 * 512 + 128 * 512]; // weights hi ([N][K])
__device__ __nv_bfloat16 g_wl[3 * 512 * 512 + 128 * 512]; // weights lo
__device__ float g_dinv[NMAX];
__device__ int   g_cnt[NMAX];
__device__ int   g_rowptr[NMAX + 1];
__device__ int   g_cursor[NMAX];
__device__ int   g_col[EMAX];

// ---------------------------------------------------------------------------
// helpers
// ---------------------------------------------------------------------------
__device__ __forceinline__ void split_pair(float x, float y, uint32_t& hi, uint32_t& lo) {
    __nv_bfloat162 h = __floats2bfloat162_rn(x, y);
    float rx = x - __bfloat162float(h.x);
    float ry = y - __bfloat162float(h.y);
    __nv_bfloat162 l = __floats2bfloat162_rn(rx, ry);
    hi = *reinterpret_cast<uint32_t*>(&h);
    lo = *reinterpret_cast<uint32_t*>(&l);
}

#define CP_ASYNC16(dst, src) \
    asm volatile("cp.async.cg.shared.global [%0], [%1], 16;" :: "r"(dst), "l"(src))
#define CP_COMMIT() asm volatile("cp.async.commit_group;")
#define CP_WAIT0()  asm volatile("cp.async.wait_group 0;")
#define CP_WAIT1()  asm volatile("cp.async.wait_group 1;")

#define LDSM4(R, addr) \
    asm volatile("ldmatrix.sync.aligned.m8n8.x4.shared.b16 {%0,%1,%2,%3}, [%4];" \
                 : "=r"((R)[0]), "=r"((R)[1]), "=r"((R)[2]), "=r"((R)[3]) : "r"(addr))

#define MMA16816(d, a, b) \
    asm volatile("mma.sync.aligned.m16n8k16.row.col.f32.bf16.bf16.f32 " \
                 "{%0,%1,%2,%3}, {%4,%5,%6,%7}, {%8,%9}, {%0,%1,%2,%3};" \
                 : "+f"((d)[0]), "+f"((d)[1]), "+f"((d)[2]), "+f"((d)[3]) \
                 : "r"((a)[0]), "r"((a)[1]), "r"((a)[2]), "r"((a)[3]), \
                   "r"((b)[0]), "r"((b)[1]))

// ---------------------------------------------------------------------------
// CSR build (unchanged from R10-pass)
// ---------------------------------------------------------------------------
__global__ void zero_cnt(int* cnt, int n) {
    int i = blockIdx.x * blockDim.x + threadIdx.x;
    if (i < n) cnt[i] = 0;
}
__global__ void hist_kernel(int* cnt, const int* __restrict__ dst, int E) {
    int e = blockIdx.x * blockDim.x + threadIdx.x;
    if (e < E) {
        int d = dst[e];
        if (d >= 0 && d < NMAX) atomicAdd(&cnt[d], 1);
    }
}
__global__ __launch_bounds__(256) void scan_kernel(
    const int* __restrict__ cnt, int* rowptr, int* cursor, float* dinv, int n)
{
    __shared__ int warpsum[8];
    const int tid  = threadIdx.x;
    const int lane = tid & 31;
    const int wrp  = tid >> 5;
    const int NT   = 256;
    const int per  = (n + NT - 1) / NT;
    const int begin = tid * per;
    const int stop  = min(begin + per, n);

    int local = 0;
    for (int i = begin; i < stop; i++) local += cnt[i];

    int v = local;
    #pragma unroll
    for (int o = 1; o < 32; o <<= 1) {
        int t = __shfl_up_sync(0xFFFFFFFFu, v, o);
        if (lane >= o) v += t;
    }
    if (lane == 31) warpsum[wrp] = v;
    __syncthreads();
    if (wrp == 0) {
        int w = (lane < 8) ? warpsum[lane] : 0;
        #pragma unroll
        for (int o = 1; o < 8; o <<= 1) {
            int t = __shfl_up_sync(0xFFFFFFFFu, w, o);
            if (lane >= o) w += t;
        }
        if (lane < 8) warpsum[lane] = w;
    }
    __syncthreads();
    int exclusive = v - local + ((wrp > 0) ? warpsum[wrp - 1] : 0);

    int run = exclusive;
    for (int i = begin; i < stop; i++) {
        rowptr[i] = run;
        cursor[i] = run;
        dinv[i]   = rsqrtf((float)cnt[i] + 1.0f);
        run += cnt[i];
    }
    if (tid == NT - 1) rowptr[n] = warpsum[7];
}
__global__ void fill_kernel(const int* __restrict__ src, const int* __restrict__ dst,
                            int* cursor, int* col, int E) {
    int e = blockIdx.x * blockDim.x + threadIdx.x;
    if (e < E) {
        int d = dst[e];
        if (d >= 0 && d < NMAX) {
            int pos = atomicAdd(&cursor[d], 1);
            if (pos >= 0 && pos < EMAX) col[pos] = src[e];
        }
    }
}

// ---------------------------------------------------------------------------
// weight convert: W [K][N] fp32 -> transposed hi/lo bf16 [N][K]
// ---------------------------------------------------------------------------
__global__ void wconv_kernel(const float* __restrict__ W,
                             __nv_bfloat16* __restrict__ oh,
                             __nv_bfloat16* __restrict__ ol, int K, int N) {
    int idx = blockIdx.x * blockDim.x + threadIdx.x;
    if (idx >= K * N) return;
    int n = idx / K, k = idx % K;
    float w = W[(size_t)k * N + n];
    __nv_bfloat16 h = __float2bfloat16_rn(w);
    float r = w - __bfloat162float(h);
    oh[idx] = h;
    ol[idx] = __float2bfloat16_rn(r);
}

// ---------------------------------------------------------------------------
// plain split for input x
// ---------------------------------------------------------------------------
__global__ void split0_kernel(const float* __restrict__ in,
                              __nv_bfloat16* __restrict__ oh,
                              __nv_bfloat16* __restrict__ ol, int M) {
    int idx = blockIdx.x * blockDim.x + threadIdx.x;
    if (idx >= M * (DF / 4)) return;
    int row = idx >> 7;
    int c = (idx & 127) * 4;
    float4 v = *reinterpret_cast<const float4*>(&in[(size_t)row * DF + c]);
    uint32_t h0, l0, h1, l1;
    split_pair(v.x, v.y, h0, l0);
    split_pair(v.z, v.w, h1, l1);
    *reinterpret_cast<uint2*>(&oh[(size_t)row * DF + c]) = make_uint2(h0, h1);
    *reinterpret_cast<uint2*>(&ol[(size_t)row * DF + c]) = make_uint2(l0, l1);
}

// ---------------------------------------------------------------------------
// CSR gather + fused GCN epilogue (unchanged from R10-pass)
// ---------------------------------------------------------------------------
__global__ __launch_bounds__(256) void gather_csr(
    const float* __restrict__ hs, const int* __restrict__ rowptr,
    const int* __restrict__ col, const float* __restrict__ dinv,
    const float* __restrict__ bias,
    __nv_bfloat16* __restrict__ oh, __nv_bfloat16* __restrict__ ol, int n)
{
    int node = (blockIdx.x * blockDim.x + threadIdx.x) >> 5;
    int lane = threadIdx.x & 31;
    if (node >= n) return;

    const float4* self = reinterpret_cast<const float4*>(hs + (size_t)node * DF);
    float4 acc[4];
    #pragma unroll
    for (int i = 0; i < 4; i++) acc[i] = self[lane + 32 * i];

    int p = rowptr[node];
    int e = rowptr[node + 1];
    if (p < 0) p = 0;
    if (e > EMAX) e = EMAX;

    while (p + 2 <= e) {
        int c0 = col[p], c1 = col[p + 1];
        const float4* r0 = reinterpret_cast<const float4*>(hs + (size_t)c0 * DF);
        const float4* r1 = reinterpret_cast<const float4*>(hs + (size_t)c1 * DF);
        float4 a0[4], a1[4];
        #pragma unroll
        for (int i = 0; i < 4; i++) a0[i] = r0[lane + 32 * i];
        #pragma unroll
        for (int i = 0; i < 4; i++) a1[i] = r1[lane + 32 * i];
        #pragma unroll
        for (int i = 0; i < 4; i++) {
            acc[i].x += a0[i].x + a1[i].x;
            acc[i].y += a0[i].y + a1[i].y;
            acc[i].z += a0[i].z + a1[i].z;
            acc[i].w += a0[i].w + a1[i].w;
        }
        p += 2;
    }
    if (p < e) {
        const float4* r0 = reinterpret_cast<const float4*>(hs + (size_t)col[p] * DF);
        #pragma unroll
        for (int i = 0; i < 4; i++) {
            float4 a = r0[lane + 32 * i];
            acc[i].x += a.x; acc[i].y += a.y; acc[i].z += a.z; acc[i].w += a.w;
        }
    }

    const float dv = dinv[node];
    const float4* bias4 = reinterpret_cast<const float4*>(bias);
    #pragma unroll
    for (int i = 0; i < 4; i++) {
        int f = lane + 32 * i;
        int c = f * 4;
        float4 bv = bias4[f];
        float x0 = fmaxf(acc[i].x * dv + bv.x, 0.f);
        float x1 = fmaxf(acc[i].y * dv + bv.y, 0.f);
        float x2 = fmaxf(acc[i].z * dv + bv.z, 0.f);
        float x3 = fmaxf(acc[i].w * dv + bv.w, 0.f);
        uint32_t h0, l0, h1, l1;
        split_pair(x0, x1, h0, l0);
        split_pair(x2, x3, h1, l1);
        *reinterpret_cast<uint2*>(&oh[(size_t)node * DF + c]) = make_uint2(h0, h1);
        *reinterpret_cast<uint2*>(&ol[(size_t)node * DF + c]) = make_uint2(l0, l1);
    }
}

// ---------------------------------------------------------------------------
// bf16x3 tensor-core GEMM — BM=128 x BN=128, warp tile 64x32 (2m x 4n),
// 3-stage cp.async, XOR swizzle, 48KB static smem, 2 CTAs/SM.
// Rationale: 64x32 warp tiles give 33 FLOP per ldmatrix byte vs 24 for the
// 64x128-CTA config — the smem crossbar is the binding resource at multi-CTA
// residency, so FLOP/B sets throughput.
//  EMODE 1: C = acc * dinv[row]
//  EMODE 2: r = relu(acc+obias); Oh/Ol = split(r)
//  EMODE 3: C = acc + obias
// ---------------------------------------------------------------------------
#define SROW 32
#define STAGE_BYTES 16384        // 4 tiles * 128 * 32
#define OFF_AL 4096
#define OFF_BH 8192
#define OFF_BL 12288

template<int EMODE>
__global__ __launch_bounds__(256, 2) void gemm_bf16x3(
    const __nv_bfloat16* __restrict__ Ah, const __nv_bfloat16* __restrict__ Al,
    const __nv_bfloat16* __restrict__ Bh, const __nv_bfloat16* __restrict__ Bl,
    float* __restrict__ C,
    __nv_bfloat16* __restrict__ Oh, __nv_bfloat16* __restrict__ Ol,
    const float* __restrict__ obias, const float* __restrict__ dinv,
    int M, int N)
{
    __shared__ __align__(16) char smem[3 * STAGE_BYTES];

    const int tid  = threadIdx.x;
    const int lane = tid & 31;
    const int wid  = tid >> 5;
    const int wm   = wid >> 2;   // 0..1 -> 64 rows each
    const int wn   = wid & 3;    // 0..3 -> 32 cols each
    const int bm   = blockIdx.y * 128;
    const int bn   = blockIdx.x * 128;

    const uint32_t sb = (uint32_t)__cvta_generic_to_shared(smem);

    // loader: thread -> (row 0..127, logical 16B chunk 0..1)
    const int lrow   = tid >> 1;
    const int lchunk = tid & 1;
    const int pchunk = lchunk ^ ((lrow >> 2) & 1);      // swizzled
    const int lce    = lchunk * 8;

    const int arow = min(bm + lrow, M - 1);
    const int brow = bn + lrow;
    const __nv_bfloat16* gAh = Ah + (size_t)arow * DF + lce;
    const __nv_bfloat16* gAl = Al + (size_t)arow * DF + lce;
    const __nv_bfloat16* gBh = Bh + (size_t)brow * DF + lce;
    const __nv_bfloat16* gBl = Bl + (size_t)brow * DF + lce;
    const uint32_t sdst = sb + lrow * SROW + pchunk * 16;

    float acc[4][4][4];
    #pragma unroll
    for (int i = 0; i < 4; i++)
        #pragma unroll
        for (int j = 0; j < 4; j++)
            #pragma unroll
            for (int k = 0; k < 4; k++) acc[i][j][k] = 0.f;

    const int NSTAGE = DF / 16;   // 32

    // prologue: stages 0 and 1 in flight
    #pragma unroll
    for (int st = 0; st < 2; st++) {
        int koff = st * 16;
        uint32_t d = sdst + st * STAGE_BYTES;
        CP_ASYNC16(d,          gAh + koff);
        CP_ASYNC16(d + OFF_AL, gAl + koff);
        CP_ASYNC16(d + OFF_BH, gBh + koff);
        CP_ASYNC16(d + OFF_BL, gBl + koff);
        CP_COMMIT();
    }

    // ldmatrix lane coords
    const int ar  = (lane & 7) + ((lane >> 3) & 1) * 8;
    const int akl = (lane >> 4) & 1;                 // A logical k-chunk
    const int br  = (lane & 7) + ((lane >> 4) & 1) * 8;
    const int bkl = (lane >> 3) & 1;                 // B logical k-chunk

    int slot = 0;
    for (int s = 0; s < NSTAGE; s++) {
        if (s + 1 < NSTAGE) { CP_WAIT1(); } else { CP_WAIT0(); }
        __syncthreads();

        // prefetch stage s+2 into slot (s+2)%3
        if (s + 2 < NSTAGE) {
            int koff = (s + 2) * 16;
            int ps = slot + 2; if (ps >= 3) ps -= 3;
            uint32_t d = sdst + ps * STAGE_BYTES;
            CP_ASYNC16(d,          gAh + koff);
            CP_ASYNC16(d + OFF_AL, gAl + koff);
            CP_ASYNC16(d + OFF_BH, gBh + koff);
            CP_ASYNC16(d + OFF_BL, gBl + koff);
            CP_COMMIT();
        }

        const uint32_t s0 = sb + slot * STAGE_BYTES;

        uint32_t ahf[4][4], alf[4][4], bhf[4][2], blf[4][2];
        #pragma unroll
        for (int mt = 0; mt < 4; mt++) {
            int row = wm * 64 + mt * 16 + ar;
            uint32_t ad = s0 + row * SROW + ((akl ^ ((row >> 2) & 1)) * 16);
            LDSM4(ahf[mt], ad);
            LDSM4(alf[mt], ad + OFF_AL);
        }
        #pragma unroll
        for (int h = 0; h < 2; h++) {
            int row = wn * 32 + h * 16 + br;
            uint32_t bd = s0 + OFF_BH + row * SROW + ((bkl ^ ((row >> 2) & 1)) * 16);
            uint32_t r[4];
            LDSM4(r, bd);
            bhf[h * 2][0] = r[0]; bhf[h * 2][1] = r[1];
            bhf[h * 2 + 1][0] = r[2]; bhf[h * 2 + 1][1] = r[3];
            LDSM4(r, bd + (OFF_BL - OFF_BH));
            blf[h * 2][0] = r[0]; blf[h * 2][1] = r[1];
            blf[h * 2 + 1][0] = r[2]; blf[h * 2 + 1][1] = r[3];
        }

        #pragma unroll
        for (int mt = 0; mt < 4; mt++)
            #pragma unroll
            for (int nt = 0; nt < 4; nt++) {
                MMA16816(acc[mt][nt], ahf[mt], bhf[nt]);
                MMA16816(acc[mt][nt], alf[mt], bhf[nt]);
                MMA16816(acc[mt][nt], ahf[mt], blf[nt]);
            }

        if (++slot == 3) slot = 0;
    }

    #pragma unroll
    for (int mt = 0; mt < 4; mt++) {
        int rbase = bm + wm * 64 + mt * 16 + (lane >> 2);
        #pragma unroll
        for (int half = 0; half < 2; half++) {
            int r = rbase + half * 8;
            if (r >= M) continue;
            float dv = (EMODE == 1) ? dinv[r] : 0.f;
            #pragma unroll
            for (int nt = 0; nt < 4; nt++) {
                int c = bn + wn * 32 + nt * 8 + (lane & 3) * 2;
                float x = acc[mt][nt][half * 2];
                float y = acc[mt][nt][half * 2 + 1];
                if (EMODE == 1) {
                    x *= dv; y *= dv;
                    *reinterpret_cast<float2*>(&C[(size_t)r * N + c]) = make_float2(x, y);
                } else if (EMODE == 2) {
                    x = fmaxf(x + obias[c], 0.f);
                    y = fmaxf(y + obias[c + 1], 0.f);
                    uint32_t hi, lo;
                    split_pair(x, y, hi, lo);
                    *reinterpret_cast<uint32_t*>(&Oh[(size_t)r * DF + c]) = hi;
                    *reinterpret_cast<uint32_t*>(&Ol[(size_t)r * DF + c]) = lo;
                } else {
                    x += obias[c];
                    y += obias[c + 1];
                    *reinterpret_cast<float2*>(&C[(size_t)r * N + c]) = make_float2(x, y);
                }
            }
        }
    }
}

// ---------------------------------------------------------------------------
// row softmax over 128 cols: one warp per row
// ---------------------------------------------------------------------------
__global__ __launch_bounds__(256) void softmax128(
    const float* __restrict__ in, float* __restrict__ out, int n)
{
    int row  = (blockIdx.x * blockDim.x + threadIdx.x) >> 5;
    int lane = threadIdx.x & 31;
    if (row >= n) return;
    float4 v = reinterpret_cast<const float4*>(in + (size_t)row * 128)[lane];
    float m = fmaxf(fmaxf(v.x, v.y), fmaxf(v.z, v.w));
    #pragma unroll
    for (int o = 16; o > 0; o >>= 1) m = fmaxf(m, __shfl_xor_sync(0xFFFFFFFFu, m, o));
    float e0 = expf(v.x - m), e1 = expf(v.y - m), e2 = expf(v.z - m), e3 = expf(v.w - m);
    float s = e0 + e1 + e2 + e3;
    #pragma unroll
    for (int o = 16; o > 0; o >>= 1) s += __shfl_xor_sync(0xFFFFFFFFu, s, o);
    float inv = 1.0f / s;
    reinterpret_cast<float4*>(out + (size_t)row * 128)[lane] =
        make_float4(e0 * inv, e1 * inv, e2 * inv, e3 * inv);
}

// ---------------------------------------------------------------------------
// kernel_launch — inputs: x, edge_index, W1, b1, W2, b2, Wf1, bf1, Wf2, bf2
// ---------------------------------------------------------------------------
extern "C" void kernel_launch(void* const* d_in, const int* in_sizes, int n_in,
                              void* d_out, int out_size)
{
    const float* x   = (const float*)d_in[0];
    const int*   ei  = (const int*)  d_in[1];
    const float* W1  = (const float*)d_in[2];
    const float* b1  = (const float*)d_in[3];
    const float* W2  = (const float*)d_in[4];
    const float* b2  = (const float*)d_in[5];
    const float* Wf1 = (const float*)d_in[6];
    const float* bf1 = (const float*)d_in[7];
    const float* Wf2 = (const float*)d_in[8];
    const float* bf2 = (const float*)d_in[9];

    const int NV = in_sizes[0] / DF;   // 20000
    const int E  = in_sizes[1] / 2;    // 320000
    const int* srcIdx = ei;
    const int* dstIdx = ei + E;

    float *bufA, *dinv;
    __nv_bfloat16 *ah, *al, *bh, *bl, *wh, *wl;
    int *cnt, *rowptr, *cursor, *col;
    cudaGetSymbolAddress((void**)&bufA, g_bufA);
    cudaGetSymbolAddress((void**)&dinv, g_dinv);
    cudaGetSymbolAddress((void**)&ah, g_ah);
    cudaGetSymbolAddress((void**)&al, g_al);
    cudaGetSymbolAddress((void**)&bh, g_bh);
    cudaGetSymbolAddress((void**)&bl, g_bl);
    cudaGetSymbolAddress((void**)&wh, g_wh);
    cudaGetSymbolAddress((void**)&wl, g_wl);
    cudaGetSymbolAddress((void**)&cnt, g_cnt);
    cudaGetSymbolAddress((void**)&rowptr, g_rowptr);
    cudaGetSymbolAddress((void**)&cursor, g_cursor);
    cudaGetSymbolAddress((void**)&col, g_col);

    const size_t W1o = 0, W2o = 512 * 512, Wf1o = 2 * 512 * 512, Wf2o = 3 * 512 * 512;

    const int nb  = (NV + 255) / 256;
    const int eb  = (E + 255) / 256;
    const int gwb = (NV * 32 + 255) / 256;
    const int smb = (NV * 32 + 255) / 256;
    const int spb = (NV * 128 + 255) / 256;

    // CSR build (also produces dinv)
    zero_cnt   <<<nb, 256>>>(cnt, NV);
    hist_kernel<<<eb, 256>>>(cnt, dstIdx, E);
    scan_kernel<<<1, 256>>>(cnt, rowptr, cursor, dinv, NV);
    fill_kernel<<<eb, 256>>>(srcIdx, dstIdx, cursor, col, E);

    // weight convert
    wconv_kernel<<<(512 * 512 + 255) / 256, 256>>>(W1,  wh + W1o,  wl + W1o,  512, 512);
    wconv_kernel<<<(512 * 512 + 255) / 256, 256>>>(W2,  wh + W2o,  wl + W2o,  512, 512);
    wconv_kernel<<<(512 * 512 + 255) / 256, 256>>>(Wf1, wh + Wf1o, wl + Wf1o, 512, 512);
    wconv_kernel<<<(512 * 128 + 255) / 256, 256>>>(Wf2, wh + Wf2o, wl + Wf2o, 512, 128);

    dim3 blk(256);
    dim3 g512(4, (NV + 127) / 128);   // BM=128 m-tiles
    dim3 g128(1, (NV + 127) / 128);

    // layer 1
    split0_kernel<<<spb, 256>>>(x, ah, al, NV);
    gemm_bf16x3<1><<<g512, blk>>>(ah, al, wh + W1o, wl + W1o,
                                  bufA, nullptr, nullptr, nullptr, dinv, NV, 512);
    gather_csr<<<gwb, 256>>>(bufA, rowptr, col, dinv, b1, ah, al, NV);

    // layer 2
    gemm_bf16x3<1><<<g512, blk>>>(ah, al, wh + W2o, wl + W2o,
                                  bufA, nullptr, nullptr, nullptr, dinv, NV, 512);
    gather_csr<<<gwb, 256>>>(bufA, rowptr, col, dinv, b2, ah, al, NV);

    // fc1
    gemm_bf16x3<2><<<g512, blk>>>(ah, al, wh + Wf1o, wl + Wf1o,
                                  nullptr, bh, bl, bf1, nullptr, NV, 512);

    // fc2
    gemm_bf16x3<3><<<g128, blk>>>(bh, bl, wh + Wf2o, wl + Wf2o,
                                  bufA, nullptr, nullptr, bf2, nullptr, NV, 128);

    // softmax -> d_out
    softmax128<<<smb, 256>>>(bufA, (float*)d_out, NV);
}

// round 14
// speedup vs baseline: 1.0915x; 1.0915x over previous
#include <cuda_runtime.h>
#include <cuda_bf16.h>
#include <cstdint>

#define NMAX 20000
#define EMAX 400000
#define DF   512

// ---------------- scratch (static device globals; no allocs) ----------------
__device__ float g_bufA[(size_t)NMAX * DF];        // fp32 hs
__device__ __nv_bfloat16 g_ah[(size_t)NMAX * DF];  // activation hi
__device__ __nv_bfloat16 g_al[(size_t)NMAX * DF];  // activation lo
__device__ __nv_bfloat16 g_bh[(size_t)NMAX * DF];  // fc1-out hi
__device__ __nv_bfloat16 g_bl[(size_t)NMAX * DF];  // fc1-out lo
__device__ __nv_bfloat16 g_wh[3 * 512 * 512 + 128 * 512]; // weights hi ([N][K])
__device__ __nv_bfloat16 g_wl[3 * 512 * 512 + 128 * 512]; // weights lo
__device__ float g_dinv[NMAX];
__device__ int   g_cnt[NMAX];
__device__ int   g_rowptr[NMAX + 1];
__device__ int   g_cursor[NMAX];
__device__ int   g_col[EMAX];

// ---------------------------------------------------------------------------
// helpers
// ---------------------------------------------------------------------------
__device__ __forceinline__ void split_pair(float x, float y, uint32_t& hi, uint32_t& lo) {
    __nv_bfloat162 h = __floats2bfloat162_rn(x, y);
    float rx = x - __bfloat162float(h.x);
    float ry = y - __bfloat162float(h.y);
    __nv_bfloat162 l = __floats2bfloat162_rn(rx, ry);
    hi = *reinterpret_cast<uint32_t*>(&h);
    lo = *reinterpret_cast<uint32_t*>(&l);
}

#define CP_ASYNC16(dst, src) \
    asm volatile("cp.async.cg.shared.global [%0], [%1], 16;" :: "r"(dst), "l"(src))
#define CP_COMMIT() asm volatile("cp.async.commit_group;")
#define CP_WAIT0()  asm volatile("cp.async.wait_group 0;")
#define CP_WAIT1()  asm volatile("cp.async.wait_group 1;")

#define LDSM4(R, addr) \
    asm volatile("ldmatrix.sync.aligned.m8n8.x4.shared.b16 {%0,%1,%2,%3}, [%4];" \
                 : "=r"((R)[0]), "=r"((R)[1]), "=r"((R)[2]), "=r"((R)[3]) : "r"(addr))

#define MMA16816(d, a, b) \
    asm volatile("mma.sync.aligned.m16n8k16.row.col.f32.bf16.bf16.f32 " \
                 "{%0,%1,%2,%3}, {%4,%5,%6,%7}, {%8,%9}, {%0,%1,%2,%3};" \
                 : "+f"((d)[0]), "+f"((d)[1]), "+f"((d)[2]), "+f"((d)[3]) \
                 : "r"((a)[0]), "r"((a)[1]), "r"((a)[2]), "r"((a)[3]), \
                   "r"((b)[0]), "r"((b)[1]))

// ---------------------------------------------------------------------------
// CSR build
// ---------------------------------------------------------------------------
__global__ void zero_cnt(int* cnt, int n) {
    int i = blockIdx.x * blockDim.x + threadIdx.x;
    if (i < n) cnt[i] = 0;
}
__global__ void hist_kernel(int* cnt, const int* __restrict__ dst, int E) {
    int e = blockIdx.x * blockDim.x + threadIdx.x;
    if (e < E) {
        int d = dst[e];
        if (d >= 0 && d < NMAX) atomicAdd(&cnt[d], 1);
    }
}
__global__ __launch_bounds__(256) void scan_kernel(
    const int* __restrict__ cnt, int* rowptr, int* cursor, float* dinv, int n)
{
    __shared__ int warpsum[8];
    const int tid  = threadIdx.x;
    const int lane = tid & 31;
    const int wrp  = tid >> 5;
    const int NT   = 256;
    const int per  = (n + NT - 1) / NT;
    const int begin = tid * per;
    const int stop  = min(begin + per, n);

    int local = 0;
    for (int i = begin; i < stop; i++) local += cnt[i];

    int v = local;
    #pragma unroll
    for (int o = 1; o < 32; o <<= 1) {
        int t = __shfl_up_sync(0xFFFFFFFFu, v, o);
        if (lane >= o) v += t;
    }
    if (lane == 31) warpsum[wrp] = v;
    __syncthreads();
    if (wrp == 0) {
        int w = (lane < 8) ? warpsum[lane] : 0;
        #pragma unroll
        for (int o = 1; o < 8; o <<= 1) {
            int t = __shfl_up_sync(0xFFFFFFFFu, w, o);
            if (lane >= o) w += t;
        }
        if (lane < 8) warpsum[lane] = w;
    }
    __syncthreads();
    int exclusive = v - local + ((wrp > 0) ? warpsum[wrp - 1] : 0);

    int run = exclusive;
    for (int i = begin; i < stop; i++) {
        rowptr[i] = run;
        cursor[i] = run;
        dinv[i]   = rsqrtf((float)cnt[i] + 1.0f);
        run += cnt[i];
    }
    if (tid == NT - 1) rowptr[n] = warpsum[7];
}
__global__ void fill_kernel(const int* __restrict__ src, const int* __restrict__ dst,
                            int* cursor, int* col, int E) {
    int e = blockIdx.x * blockDim.x + threadIdx.x;
    if (e < E) {
        int d = dst[e];
        if (d >= 0 && d < NMAX) {
            int pos = atomicAdd(&cursor[d], 1);
            if (pos >= 0 && pos < EMAX) col[pos] = src[e];
        }
    }
}

// ---------------------------------------------------------------------------
// merged weight convert: all 4 matrices in one launch (512-thread blocks).
// ---------------------------------------------------------------------------
__global__ void wconv_all(const float* __restrict__ W1, const float* __restrict__ W2,
                          const float* __restrict__ Wf1, const float* __restrict__ Wf2,
                          __nv_bfloat16* __restrict__ oh, __nv_bfloat16* __restrict__ ol)
{
    const int S = 512 * 512;
    const int TOTAL = 3 * S + 128 * 512;
    int idx = blockIdx.x * blockDim.x + threadIdx.x;
    if (idx >= TOTAL) return;
    const float* W; int local; int Ncols;
    if (idx < S)            { W = W1;  local = idx;         Ncols = 512; }
    else if (idx < 2 * S)   { W = W2;  local = idx - S;     Ncols = 512; }
    else if (idx < 3 * S)   { W = Wf1; local = idx - 2 * S; Ncols = 512; }
    else                    { W = Wf2; local = idx - 3 * S; Ncols = 128; }
    int n = local >> 9, k = local & 511;
    float w = W[(size_t)k * Ncols + n];
    __nv_bfloat16 h = __float2bfloat16_rn(w);
    float r = w - __bfloat162float(h);
    oh[idx] = h;
    ol[idx] = __float2bfloat16_rn(r);
}

// ---------------------------------------------------------------------------
// plain split for input x
// ---------------------------------------------------------------------------
__global__ void split0_kernel(const float* __restrict__ in,
                              __nv_bfloat16* __restrict__ oh,
                              __nv_bfloat16* __restrict__ ol, int M) {
    int idx = blockIdx.x * blockDim.x + threadIdx.x;
    if (idx >= M * (DF / 4)) return;
    int row = idx >> 7;
    int c = (idx & 127) * 4;
    float4 v = *reinterpret_cast<const float4*>(&in[(size_t)row * DF + c]);
    uint32_t h0, l0, h1, l1;
    split_pair(v.x, v.y, h0, l0);
    split_pair(v.z, v.w, h1, l1);
    *reinterpret_cast<uint2*>(&oh[(size_t)row * DF + c]) = make_uint2(h0, h1);
    *reinterpret_cast<uint2*>(&ol[(size_t)row * DF + c]) = make_uint2(l0, l1);
}

// ---------------------------------------------------------------------------
// CSR gather + fused GCN epilogue: one warp per node, 128-thread blocks.
// ---------------------------------------------------------------------------
__global__ __launch_bounds__(128) void gather_csr(
    const float* __restrict__ hs, const int* __restrict__ rowptr,
    const int* __restrict__ col, const float* __restrict__ dinv,
    const float* __restrict__ bias,
    __nv_bfloat16* __restrict__ oh, __nv_bfloat16* __restrict__ ol, int n)
{
    int node = (blockIdx.x * blockDim.x + threadIdx.x) >> 5;
    int lane = threadIdx.x & 31;
    if (node >= n) return;

    const float4* self = reinterpret_cast<const float4*>(hs + (size_t)node * DF);
    float4 acc[4];
    #pragma unroll
    for (int i = 0; i < 4; i++) acc[i] = self[lane + 32 * i];

    int p = rowptr[node];
    int e = rowptr[node + 1];
    if (p < 0) p = 0;
    if (e > EMAX) e = EMAX;

    while (p + 2 <= e) {
        int c0 = col[p], c1 = col[p + 1];
        const float4* r0 = reinterpret_cast<const float4*>(hs + (size_t)c0 * DF);
        const float4* r1 = reinterpret_cast<const float4*>(hs + (size_t)c1 * DF);
        float4 a0[4], a1[4];
        #pragma unroll
        for (int i = 0; i < 4; i++) a0[i] = r0[lane + 32 * i];
        #pragma unroll
        for (int i = 0; i < 4; i++) a1[i] = r1[lane + 32 * i];
        #pragma unroll
        for (int i = 0; i < 4; i++) {
            acc[i].x += a0[i].x + a1[i].x;
            acc[i].y += a0[i].y + a1[i].y;
            acc[i].z += a0[i].z + a1[i].z;
            acc[i].w += a0[i].w + a1[i].w;
        }
        p += 2;
    }
    if (p < e) {
        const float4* r0 = reinterpret_cast<const float4*>(hs + (size_t)col[p] * DF);
        #pragma unroll
        for (int i = 0; i < 4; i++) {
            float4 a = r0[lane + 32 * i];
            acc[i].x += a.x; acc[i].y += a.y; acc[i].z += a.z; acc[i].w += a.w;
        }
    }

    const float dv = dinv[node];
    const float4* bias4 = reinterpret_cast<const float4*>(bias);
    #pragma unroll
    for (int i = 0; i < 4; i++) {
        int f = lane + 32 * i;
        int c = f * 4;
        float4 bv = bias4[f];
        float x0 = fmaxf(acc[i].x * dv + bv.x, 0.f);
        float x1 = fmaxf(acc[i].y * dv + bv.y, 0.f);
        float x2 = fmaxf(acc[i].z * dv + bv.z, 0.f);
        float x3 = fmaxf(acc[i].w * dv + bv.w, 0.f);
        uint32_t h0, l0, h1, l1;
        split_pair(x0, x1, h0, l0);
        split_pair(x2, x3, h1, l1);
        *reinterpret_cast<uint2*>(&oh[(size_t)node * DF + c]) = make_uint2(h0, h1);
        *reinterpret_cast<uint2*>(&ol[(size_t)node * DF + c]) = make_uint2(l0, l1);
    }
}

// ---------------------------------------------------------------------------
// bf16x3 tensor-core GEMM — BM=64 x BN=128, 3-stage cp.async, XOR swizzle.
// (R10 winning config: 8 warps 2m x 4n, warp tile 32x32, 3 CTAs/SM.)
//  EMODE 1: C = acc * dinv[row]
//  EMODE 2: r = relu(acc+obias); Oh/Ol = split(r)
//  EMODE 4: t = acc + obias; block-softmax over the 128-col row; C = softmax
// ---------------------------------------------------------------------------
#define SROW 32
#define STAGE_BYTES 12288
#define OFF_AL 2048
#define OFF_BH 4096
#define OFF_BL 8192

template<int EMODE>
__global__ __launch_bounds__(256, 3) void gemm_bf16x3(
    const __nv_bfloat16* __restrict__ Ah, const __nv_bfloat16* __restrict__ Al,
    const __nv_bfloat16* __restrict__ Bh, const __nv_bfloat16* __restrict__ Bl,
    float* __restrict__ C,
    __nv_bfloat16* __restrict__ Oh, __nv_bfloat16* __restrict__ Ol,
    const float* __restrict__ obias, const float* __restrict__ dinv,
    int M, int N)
{
    __shared__ __align__(16) char smem[3 * STAGE_BYTES];
    __shared__ float rred[64][4];        // softmax cross-warp reduction (EMODE 4)

    const int tid  = threadIdx.x;
    const int lane = tid & 31;
    const int wid  = tid >> 5;
    const int wm   = wid >> 2;   // 0..1 (32 rows each)
    const int wn   = wid & 3;    // 0..3 (32 cols each)
    const int bm   = blockIdx.y * 64;
    const int bn   = blockIdx.x * 128;

    const uint32_t sb = (uint32_t)__cvta_generic_to_shared(smem);

    // loader coords
    const int lrow   = tid >> 1;           // B rows 0..127; A rows 0..63 (tid<128)
    const int lchunk = tid & 1;
    const int pchunk = lchunk ^ ((lrow >> 2) & 1);
    const int lce    = lchunk * 8;

    const int brow = bn + lrow;
    const __nv_bfloat16* gBh = Bh + (size_t)brow * DF + lce;
    const __nv_bfloat16* gBl = Bl + (size_t)brow * DF + lce;
    const uint32_t sdstB = sb + lrow * SROW + pchunk * 16;

    const bool aload = (tid < 128);
    const int arow = min(bm + lrow, M - 1);
    const __nv_bfloat16* gAh = Ah + (size_t)arow * DF + lce;
    const __nv_bfloat16* gAl = Al + (size_t)arow * DF + lce;
    const uint32_t sdstA = sb + lrow * SROW + pchunk * 16;

    float acc[2][4][4];
    #pragma unroll
    for (int i = 0; i < 2; i++)
        #pragma unroll
        for (int j = 0; j < 4; j++)
            #pragma unroll
            for (int k = 0; k < 4; k++) acc[i][j][k] = 0.f;

    const int NSTAGE = DF / 16;   // 32

    // prologue: stages 0,1 in flight (A first — binary perturbation)
    #pragma unroll
    for (int st = 0; st < 2; st++) {
        int koff = st * 16;
        uint32_t dA = sdstA + st * STAGE_BYTES;
        uint32_t dB = sdstB + st * STAGE_BYTES;
        if (aload) {
            CP_ASYNC16(dA,          gAh + koff);
            CP_ASYNC16(dA + OFF_AL, gAl + koff);
        }
        CP_ASYNC16(dB + OFF_BH, gBh + koff);
        CP_ASYNC16(dB + OFF_BL, gBl + koff);
        CP_COMMIT();
    }

    const int ar  = (lane & 7) + ((lane >> 3) & 1) * 8;
    const int akl = (lane >> 4) & 1;
    const int br  = (lane & 7) + ((lane >> 4) & 1) * 8;
    const int bkl = (lane >> 3) & 1;

    int slot = 0;
    for (int s = 0; s < NSTAGE; s++) {
        if (s + 1 < NSTAGE) { CP_WAIT1(); } else { CP_WAIT0(); }
        __syncthreads();

        if (s + 2 < NSTAGE) {
            int koff = (s + 2) * 16;
            int ps = slot + 2; if (ps >= 3) ps -= 3;
            uint32_t dA = sdstA + ps * STAGE_BYTES;
            uint32_t dB = sdstB + ps * STAGE_BYTES;
            if (aload) {
                CP_ASYNC16(dA,          gAh + koff);
                CP_ASYNC16(dA + OFF_AL, gAl + koff);
            }
            CP_ASYNC16(dB + OFF_BH, gBh + koff);
            CP_ASYNC16(dB + OFF_BL, gBl + koff);
            CP_COMMIT();
        }

        const uint32_t s0 = sb + slot * STAGE_BYTES;

        uint32_t ahf[2][4], alf[2][4], bhf[4][2], blf[4][2];
        #pragma unroll
        for (int mt = 0; mt < 2; mt++) {
            int row = wm * 32 + mt * 16 + ar;
            uint32_t ad = s0 + row * SROW + ((akl ^ ((row >> 2) & 1)) * 16);
            LDSM4(ahf[mt], ad);
            LDSM4(alf[mt], ad + OFF_AL);
        }
        #pragma unroll
        for (int h = 0; h < 2; h++) {
            int row = wn * 32 + h * 16 + br;
            uint32_t bd = s0 + OFF_BH + row * SROW + ((bkl ^ ((row >> 2) & 1)) * 16);
            uint32_t r[4];
            LDSM4(r, bd);
            bhf[h * 2][0] = r[0]; bhf[h * 2][1] = r[1];
            bhf[h * 2 + 1][0] = r[2]; bhf[h * 2 + 1][1] = r[3];
            LDSM4(r, bd + (OFF_BL - OFF_BH));
            blf[h * 2][0] = r[0]; blf[h * 2][1] = r[1];
            blf[h * 2 + 1][0] = r[2]; blf[h * 2 + 1][1] = r[3];
        }

        #pragma unroll
        for (int mt = 0; mt < 2; mt++)
            #pragma unroll
            for (int nt = 0; nt < 4; nt++) {
                MMA16816(acc[mt][nt], ahf[mt], bhf[nt]);
                MMA16816(acc[mt][nt], alf[mt], bhf[nt]);
                MMA16816(acc[mt][nt], ahf[mt], blf[nt]);
            }

        if (++slot == 3) slot = 0;
    }

    if (EMODE == 4) {
        // ---- fused bias + row softmax (N == 128, bn == 0) ----
        #pragma unroll
        for (int mt = 0; mt < 2; mt++)
            #pragma unroll
            for (int half = 0; half < 2; half++)
                #pragma unroll
                for (int nt = 0; nt < 4; nt++) {
                    int c = wn * 32 + nt * 8 + (lane & 3) * 2;
                    acc[mt][nt][half * 2]     += obias[c];
                    acc[mt][nt][half * 2 + 1] += obias[c + 1];
                }
        float lm[2][2];
        #pragma unroll
        for (int mt = 0; mt < 2; mt++)
            #pragma unroll
            for (int half = 0; half < 2; half++) {
                float m = -3.4e38f;
                #pragma unroll
                for (int nt = 0; nt < 4; nt++) {
                    m = fmaxf(m, acc[mt][nt][half * 2]);
                    m = fmaxf(m, acc[mt][nt][half * 2 + 1]);
                }
                m = fmaxf(m, __shfl_xor_sync(0xFFFFFFFFu, m, 1));
                m = fmaxf(m, __shfl_xor_sync(0xFFFFFFFFu, m, 2));
                lm[mt][half] = m;
            }
        __syncthreads();
        if ((lane & 3) == 0) {
            #pragma unroll
            for (int mt = 0; mt < 2; mt++)
                #pragma unroll
                for (int half = 0; half < 2; half++) {
                    int rb = wm * 32 + mt * 16 + half * 8 + (lane >> 2);
                    rred[rb][wn] = lm[mt][half];
                }
        }
        __syncthreads();
        float Mrow[2][2];
        #pragma unroll
        for (int mt = 0; mt < 2; mt++)
            #pragma unroll
            for (int half = 0; half < 2; half++) {
                int rb = wm * 32 + mt * 16 + half * 8 + (lane >> 2);
                Mrow[mt][half] = fmaxf(fmaxf(rred[rb][0], rred[rb][1]),
                                       fmaxf(rred[rb][2], rred[rb][3]));
            }
        __syncthreads();
        float ls[2][2];
        #pragma unroll
        for (int mt = 0; mt < 2; mt++)
            #pragma unroll
            for (int half = 0; half < 2; half++) {
                float s = 0.f;
                #pragma unroll
                for (int nt = 0; nt < 4; nt++) {
                    float e0 = expf(acc[mt][nt][half * 2]     - Mrow[mt][half]);
                    float e1 = expf(acc[mt][nt][half * 2 + 1] - Mrow[mt][half]);
                    acc[mt][nt][half * 2]     = e0;
                    acc[mt][nt][half * 2 + 1] = e1;
                    s += e0 + e1;
                }
                s += __shfl_xor_sync(0xFFFFFFFFu, s, 1);
                s += __shfl_xor_sync(0xFFFFFFFFu, s, 2);
                ls[mt][half] = s;
            }
        if ((lane & 3) == 0) {
            #pragma unroll
            for (int mt = 0; mt < 2; mt++)
                #pragma unroll
                for (int half = 0; half < 2; half++) {
                    int rb = wm * 32 + mt * 16 + half * 8 + (lane >> 2);
                    rred[rb][wn] = ls[mt][half];
                }
        }
        __syncthreads();
        #pragma unroll
        for (int mt = 0; mt < 2; mt++)
            #pragma unroll
            for (int half = 0; half < 2; half++) {
                int rb = wm * 32 + mt * 16 + half * 8 + (lane >> 2);
                int r  = bm + rb;
                if (r >= M) continue;
                float inv = 1.0f / (rred[rb][0] + rred[rb][1] + rred[rb][2] + rred[rb][3]);
                #pragma unroll
                for (int nt = 0; nt < 4; nt++) {
                    int c = wn * 32 + nt * 8 + (lane & 3) * 2;
                    *reinterpret_cast<float2*>(&C[(size_t)r * N + c]) =
                        make_float2(acc[mt][nt][half * 2] * inv,
                                    acc[mt][nt][half * 2 + 1] * inv);
                }
            }
        return;
    }

    // ---- standard epilogues ----
    #pragma unroll
    for (int mt = 0; mt < 2; mt++) {
        int rbase = bm + wm * 32 + mt * 16 + (lane >> 2);
        #pragma unroll
        for (int half = 0; half < 2; half++) {
            int r = rbase + half * 8;
            if (r >= M) continue;
            float dv = (EMODE == 1) ? dinv[r] : 0.f;
            #pragma unroll
            for (int nt = 0; nt < 4; nt++) {
                int c = bn + wn * 32 + nt * 8 + (lane & 3) * 2;
                float x = acc[mt][nt][half * 2];
                float y = acc[mt][nt][half * 2 + 1];
                if (EMODE == 1) {
                    x *= dv; y *= dv;
                    *reinterpret_cast<float2*>(&C[(size_t)r * N + c]) = make_float2(x, y);
                } else if (EMODE == 2) {
                    x = fmaxf(x + obias[c], 0.f);
                    y = fmaxf(y + obias[c + 1], 0.f);
                    uint32_t hi, lo;
                    split_pair(x, y, hi, lo);
                    *reinterpret_cast<uint32_t*>(&Oh[(size_t)r * DF + c]) = hi;
                    *reinterpret_cast<uint32_t*>(&Ol[(size_t)r * DF + c]) = lo;
                }
            }
        }
    }
}

// ---------------------------------------------------------------------------
// kernel_launch — inputs: x, edge_index, W1, b1, W2, b2, Wf1, bf1, Wf2, bf2
// ---------------------------------------------------------------------------
extern "C" void kernel_launch(void* const* d_in, const int* in_sizes, int n_in,
                              void* d_out, int out_size)
{
    const float* x   = (const float*)d_in[0];
    const int*   ei  = (const int*)  d_in[1];
    const float* W1  = (const float*)d_in[2];
    const float* b1  = (const float*)d_in[3];
    const float* W2  = (const float*)d_in[4];
    const float* b2  = (const float*)d_in[5];
    const float* Wf1 = (const float*)d_in[6];
    const float* bf1 = (const float*)d_in[7];
    const float* Wf2 = (const float*)d_in[8];
    const float* bf2 = (const float*)d_in[9];

    const int NV = in_sizes[0] / DF;   // 20000
    const int E  = in_sizes[1] / 2;    // 320000
    const int* srcIdx = ei;
    const int* dstIdx = ei + E;

    float *bufA, *dinv;
    __nv_bfloat16 *ah, *al, *bh, *bl, *wh, *wl;
    int *cnt, *rowptr, *cursor, *col;
    cudaGetSymbolAddress((void**)&bufA, g_bufA);
    cudaGetSymbolAddress((void**)&dinv, g_dinv);
    cudaGetSymbolAddress((void**)&ah, g_ah);
    cudaGetSymbolAddress((void**)&al, g_al);
    cudaGetSymbolAddress((void**)&bh, g_bh);
    cudaGetSymbolAddress((void**)&bl, g_bl);
    cudaGetSymbolAddress((void**)&wh, g_wh);
    cudaGetSymbolAddress((void**)&wl, g_wl);
    cudaGetSymbolAddress((void**)&cnt, g_cnt);
    cudaGetSymbolAddress((void**)&rowptr, g_rowptr);
    cudaGetSymbolAddress((void**)&cursor, g_cursor);
    cudaGetSymbolAddress((void**)&col, g_col);

    const size_t W1o = 0, W2o = 512 * 512, Wf1o = 2 * 512 * 512, Wf2o = 3 * 512 * 512;

    const int nb  = (NV + 255) / 256;
    const int eb  = (E + 255) / 256;
    const int gwb = (NV * 32 + 127) / 128;
    const int spb = (NV * 128 + 255) / 256;
    const int wcb = (3 * 512 * 512 + 128 * 512 + 511) / 512;

    // CSR build (also produces dinv)
    zero_cnt   <<<nb, 256>>>(cnt, NV);
    hist_kernel<<<eb, 256>>>(cnt, dstIdx, E);
    scan_kernel<<<1, 256>>>(cnt, rowptr, cursor, dinv, NV);
    fill_kernel<<<eb, 256>>>(srcIdx, dstIdx, cursor, col, E);

    // merged weight convert (all 4 matrices)
    wconv_all<<<wcb, 512>>>(W1, W2, Wf1, Wf2, wh, wl);

    dim3 blk(256);
    dim3 g512(4, (NV + 63) / 64);
    dim3 g128(1, (NV + 63) / 64);

    // layer 1
    split0_kernel<<<spb, 256>>>(x, ah, al, NV);
    gemm_bf16x3<1><<<g512, blk>>>(ah, al, wh + W1o, wl + W1o,
                                  bufA, nullptr, nullptr, nullptr, dinv, NV, 512);
    gather_csr<<<gwb, 128>>>(bufA, rowptr, col, dinv, b1, ah, al, NV);

    // layer 2
    gemm_bf16x3<1><<<g512, blk>>>(ah, al, wh + W2o, wl + W2o,
                                  bufA, nullptr, nullptr, nullptr, dinv, NV, 512);
    gather_csr<<<gwb, 128>>>(bufA, rowptr, col, dinv, b2, ah, al, NV);

    // fc1
    gemm_bf16x3<2><<<g512, blk>>>(ah, al, wh + Wf1o, wl + Wf1o,
                                  nullptr, bh, bl, bf1, nullptr, NV, 512);

    // fc2 + fused softmax -> d_out
    gemm_bf16x3<4><<<g128, blk>>>(bh, bl, wh + Wf2o, wl + Wf2o,
                                  (float*)d_out, nullptr, nullptr, bf2, nullptr, NV, 128);
}

// round 15
// speedup vs baseline: 1.1303x; 1.0355x over previous
#include <cuda_runtime.h>
#include <cuda_bf16.h>
#include <cstdint>

#define NMAX 20000
#define EMAX 400000
#define DF   512

// ---------------- scratch (static device globals; no allocs) ----------------
__device__ float g_bufA[(size_t)NMAX * DF];        // fp32 hs
__device__ __nv_bfloat16 g_ah[(size_t)NMAX * DF];  // activation hi
__device__ __nv_bfloat16 g_al[(size_t)NMAX * DF];  // activation lo
__device__ __nv_bfloat16 g_bh[(size_t)NMAX * DF];  // fc1-out hi
__device__ __nv_bfloat16 g_bl[(size_t)NMAX * DF];  // fc1-out lo
__device__ __nv_bfloat16 g_wh[3 * 512 * 512 + 128 * 512]; // weights hi ([N][K])
__device__ __nv_bfloat16 g_wl[3 * 512 * 512 + 128 * 512]; // weights lo
__device__ float g_dinv[NMAX];
__device__ int   g_cnt[NMAX];
__device__ int   g_rowptr[NMAX + 1];
__device__ int   g_cursor[NMAX];
__device__ int   g_col[EMAX];

// ---------------------------------------------------------------------------
// helpers
// ---------------------------------------------------------------------------
__device__ __forceinline__ void split_pair(float x, float y, uint32_t& hi, uint32_t& lo) {
    __nv_bfloat162 h = __floats2bfloat162_rn(x, y);
    float rx = x - __bfloat162float(h.x);
    float ry = y - __bfloat162float(h.y);
    __nv_bfloat162 l = __floats2bfloat162_rn(rx, ry);
    hi = *reinterpret_cast<uint32_t*>(&h);
    lo = *reinterpret_cast<uint32_t*>(&l);
}

#define CP_ASYNC16(dst, src) \
    asm volatile("cp.async.cg.shared.global [%0], [%1], 16;" :: "r"(dst), "l"(src))
#define CP_COMMIT() asm volatile("cp.async.commit_group;")
#define CP_WAIT0()  asm volatile("cp.async.wait_group 0;")
#define CP_WAIT1()  asm volatile("cp.async.wait_group 1;")

#define LDSM4(R, addr) \
    asm volatile("ldmatrix.sync.aligned.m8n8.x4.shared.b16 {%0,%1,%2,%3}, [%4];" \
                 : "=r"((R)[0]), "=r"((R)[1]), "=r"((R)[2]), "=r"((R)[3]) : "r"(addr))

#define MMA16816(d, a, b) \
    asm volatile("mma.sync.aligned.m16n8k16.row.col.f32.bf16.bf16.f32 " \
                 "{%0,%1,%2,%3}, {%4,%5,%6,%7}, {%8,%9}, {%0,%1,%2,%3};" \
                 : "+f"((d)[0]), "+f"((d)[1]), "+f"((d)[2]), "+f"((d)[3]) \
                 : "r"((a)[0]), "r"((a)[1]), "r"((a)[2]), "r"((a)[3]), \
                   "r"((b)[0]), "r"((b)[1]))

// ---------------------------------------------------------------------------
// CSR build
// ---------------------------------------------------------------------------
__global__ void zero_cnt(int* cnt, int n) {
    int i = blockIdx.x * blockDim.x + threadIdx.x;
    if (i < n) cnt[i] = 0;
}
__global__ void hist_kernel(int* cnt, const int* __restrict__ dst, int E) {
    int e = blockIdx.x * blockDim.x + threadIdx.x;
    if (e < E) {
        int d = dst[e];
        if (d >= 0 && d < NMAX) atomicAdd(&cnt[d], 1);
    }
}
__global__ __launch_bounds__(256) void scan_kernel(
    const int* __restrict__ cnt, int* rowptr, int* cursor, float* dinv, int n)
{
    __shared__ int warpsum[8];
    const int tid  = threadIdx.x;
    const int lane = tid & 31;
    const int wrp  = tid >> 5;
    const int NT   = 256;
    const int per  = (n + NT - 1) / NT;
    const int begin = tid * per;
    const int stop  = min(begin + per, n);

    int local = 0;
    for (int i = begin; i < stop; i++) local += cnt[i];

    int v = local;
    #pragma unroll
    for (int o = 1; o < 32; o <<= 1) {
        int t = __shfl_up_sync(0xFFFFFFFFu, v, o);
        if (lane >= o) v += t;
    }
    if (lane == 31) warpsum[wrp] = v;
    __syncthreads();
    if (wrp == 0) {
        int w = (lane < 8) ? warpsum[lane] : 0;
        #pragma unroll
        for (int o = 1; o < 8; o <<= 1) {
            int t = __shfl_up_sync(0xFFFFFFFFu, w, o);
            if (lane >= o) w += t;
        }
        if (lane < 8) warpsum[lane] = w;
    }
    __syncthreads();
    int exclusive = v - local + ((wrp > 0) ? warpsum[wrp - 1] : 0);

    int run = exclusive;
    for (int i = begin; i < stop; i++) {
        rowptr[i] = run;
        cursor[i] = run;
        dinv[i]   = rsqrtf((float)cnt[i] + 1.0f);
        run += cnt[i];
    }
    if (tid == NT - 1) rowptr[n] = warpsum[7];
}
__global__ void fill_kernel(const int* __restrict__ src, const int* __restrict__ dst,
                            int* cursor, int* col, int E) {
    int e = blockIdx.x * blockDim.x + threadIdx.x;
    if (e < E) {
        int d = dst[e];
        if (d >= 0 && d < NMAX) {
            int pos = atomicAdd(&cursor[d], 1);
            if (pos >= 0 && pos < EMAX) col[pos] = src[e];
        }
    }
}

// ---------------------------------------------------------------------------
// merged weight convert: all 4 matrices in one launch.
// ---------------------------------------------------------------------------
__global__ void wconv_all(const float* __restrict__ W1, const float* __restrict__ W2,
                          const float* __restrict__ Wf1, const float* __restrict__ Wf2,
                          __nv_bfloat16* __restrict__ oh, __nv_bfloat16* __restrict__ ol)
{
    const int S = 512 * 512;
    const int TOTAL = 3 * S + 128 * 512;
    int idx = blockIdx.x * blockDim.x + threadIdx.x;
    if (idx >= TOTAL) return;
    const float* W; int local; int Ncols;
    if (idx < S)            { W = W1;  local = idx;         Ncols = 512; }
    else if (idx < 2 * S)   { W = W2;  local = idx - S;     Ncols = 512; }
    else if (idx < 3 * S)   { W = Wf1; local = idx - 2 * S; Ncols = 512; }
    else                    { W = Wf2; local = idx - 3 * S; Ncols = 128; }
    int n = local >> 9, k = local & 511;
    float w = W[(size_t)k * Ncols + n];
    __nv_bfloat16 h = __float2bfloat16_rn(w);
    float r = w - __bfloat162float(h);
    oh[idx] = h;
    ol[idx] = __float2bfloat16_rn(r);
}

// ---------------------------------------------------------------------------
// plain split for input x
// ---------------------------------------------------------------------------
__global__ void split0_kernel(const float* __restrict__ in,
                              __nv_bfloat16* __restrict__ oh,
                              __nv_bfloat16* __restrict__ ol, int M) {
    int idx = blockIdx.x * blockDim.x + threadIdx.x;
    if (idx >= M * (DF / 4)) return;
    int row = idx >> 7;
    int c = (idx & 127) * 4;
    float4 v = *reinterpret_cast<const float4*>(&in[(size_t)row * DF + c]);
    uint32_t h0, l0, h1, l1;
    split_pair(v.x, v.y, h0, l0);
    split_pair(v.z, v.w, h1, l1);
    *reinterpret_cast<uint2*>(&oh[(size_t)row * DF + c]) = make_uint2(h0, h1);
    *reinterpret_cast<uint2*>(&ol[(size_t)row * DF + c]) = make_uint2(l0, l1);
}

// ---------------------------------------------------------------------------
// CSR gather + fused GCN epilogue: one warp per node, 256-thread blocks
// (R10-proven config).
// ---------------------------------------------------------------------------
__global__ __launch_bounds__(256) void gather_csr(
    const float* __restrict__ hs, const int* __restrict__ rowptr,
    const int* __restrict__ col, const float* __restrict__ dinv,
    const float* __restrict__ bias,
    __nv_bfloat16* __restrict__ oh, __nv_bfloat16* __restrict__ ol, int n)
{
    int node = (blockIdx.x * blockDim.x + threadIdx.x) >> 5;
    int lane = threadIdx.x & 31;
    if (node >= n) return;

    const float4* self = reinterpret_cast<const float4*>(hs + (size_t)node * DF);
    float4 acc[4];
    #pragma unroll
    for (int i = 0; i < 4; i++) acc[i] = self[lane + 32 * i];

    int p = rowptr[node];
    int e = rowptr[node + 1];
    if (p < 0) p = 0;
    if (e > EMAX) e = EMAX;

    while (p + 2 <= e) {
        int c0 = col[p], c1 = col[p + 1];
        const float4* r0 = reinterpret_cast<const float4*>(hs + (size_t)c0 * DF);
        const float4* r1 = reinterpret_cast<const float4*>(hs + (size_t)c1 * DF);
        float4 a0[4], a1[4];
        #pragma unroll
        for (int i = 0; i < 4; i++) a0[i] = r0[lane + 32 * i];
        #pragma unroll
        for (int i = 0; i < 4; i++) a1[i] = r1[lane + 32 * i];
        #pragma unroll
        for (int i = 0; i < 4; i++) {
            acc[i].x += a0[i].x + a1[i].x;
            acc[i].y += a0[i].y + a1[i].y;
            acc[i].z += a0[i].z + a1[i].z;
            acc[i].w += a0[i].w + a1[i].w;
        }
        p += 2;
    }
    if (p < e) {
        const float4* r0 = reinterpret_cast<const float4*>(hs + (size_t)col[p] * DF);
        #pragma unroll
        for (int i = 0; i < 4; i++) {
            float4 a = r0[lane + 32 * i];
            acc[i].x += a.x; acc[i].y += a.y; acc[i].z += a.z; acc[i].w += a.w;
        }
    }

    const float dv = dinv[node];
    const float4* bias4 = reinterpret_cast<const float4*>(bias);
    #pragma unroll
    for (int i = 0; i < 4; i++) {
        int f = lane + 32 * i;
        int c = f * 4;
        float4 bv = bias4[f];
        float x0 = fmaxf(acc[i].x * dv + bv.x, 0.f);
        float x1 = fmaxf(acc[i].y * dv + bv.y, 0.f);
        float x2 = fmaxf(acc[i].z * dv + bv.z, 0.f);
        float x3 = fmaxf(acc[i].w * dv + bv.w, 0.f);
        uint32_t h0, l0, h1, l1;
        split_pair(x0, x1, h0, l0);
        split_pair(x2, x3, h1, l1);
        *reinterpret_cast<uint2*>(&oh[(size_t)node * DF + c]) = make_uint2(h0, h1);
        *reinterpret_cast<uint2*>(&ol[(size_t)node * DF + c]) = make_uint2(l0, l1);
    }
}

// ---------------------------------------------------------------------------
// bf16x3 tensor-core GEMM — BM=64 x BN=128, 3-stage cp.async, XOR swizzle.
// (R10 winning config: 8 warps 2m x 4n, warp tile 32x32, 3 CTAs/SM,
//  B-first prologue issue as in the R10 binary.)
//  EMODE 1: C = acc * dinv[row]
//  EMODE 2: r = relu(acc+obias); Oh/Ol = split(r)
//  EMODE 4: t = acc + obias; block-softmax over the 128-col row; C = softmax
// ---------------------------------------------------------------------------
#define SROW 32
#define STAGE_BYTES 12288
#define OFF_AL 2048
#define OFF_BH 4096
#define OFF_BL 8192

template<int EMODE>
__global__ __launch_bounds__(256, 3) void gemm_bf16x3(
    const __nv_bfloat16* __restrict__ Ah, const __nv_bfloat16* __restrict__ Al,
    const __nv_bfloat16* __restrict__ Bh, const __nv_bfloat16* __restrict__ Bl,
    float* __restrict__ C,
    __nv_bfloat16* __restrict__ Oh, __nv_bfloat16* __restrict__ Ol,
    const float* __restrict__ obias, const float* __restrict__ dinv,
    int M, int N)
{
    __shared__ __align__(16) char smem[3 * STAGE_BYTES];
    __shared__ float rred[64][4];        // softmax cross-warp reduction (EMODE 4)

    const int tid  = threadIdx.x;
    const int lane = tid & 31;
    const int wid  = tid >> 5;
    const int wm   = wid >> 2;   // 0..1 (32 rows each)
    const int wn   = wid & 3;    // 0..3 (32 cols each)
    const int bm   = blockIdx.y * 64;
    const int bn   = blockIdx.x * 128;

    const uint32_t sb = (uint32_t)__cvta_generic_to_shared(smem);

    // loader coords
    const int lrow   = tid >> 1;           // B rows 0..127; A rows 0..63 (tid<128)
    const int lchunk = tid & 1;
    const int pchunk = lchunk ^ ((lrow >> 2) & 1);
    const int lce    = lchunk * 8;

    const int brow = bn + lrow;
    const __nv_bfloat16* gBh = Bh + (size_t)brow * DF + lce;
    const __nv_bfloat16* gBl = Bl + (size_t)brow * DF + lce;
    const uint32_t sdstB = sb + lrow * SROW + pchunk * 16;

    const bool aload = (tid < 128);
    const int arow = min(bm + lrow, M - 1);
    const __nv_bfloat16* gAh = Ah + (size_t)arow * DF + lce;
    const __nv_bfloat16* gAl = Al + (size_t)arow * DF + lce;
    const uint32_t sdstA = sb + lrow * SROW + pchunk * 16;

    float acc[2][4][4];
    #pragma unroll
    for (int i = 0; i < 2; i++)
        #pragma unroll
        for (int j = 0; j < 4; j++)
            #pragma unroll
            for (int k = 0; k < 4; k++) acc[i][j][k] = 0.f;

    const int NSTAGE = DF / 16;   // 32

    // prologue: stages 0,1 in flight (B first — R10 binary order)
    #pragma unroll
    for (int st = 0; st < 2; st++) {
        int koff = st * 16;
        uint32_t dA = sdstA + st * STAGE_BYTES;
        uint32_t dB = sdstB + st * STAGE_BYTES;
        CP_ASYNC16(dB + OFF_BH, gBh + koff);
        CP_ASYNC16(dB + OFF_BL, gBl + koff);
        if (aload) {
            CP_ASYNC16(dA,          gAh + koff);
            CP_ASYNC16(dA + OFF_AL, gAl + koff);
        }
        CP_COMMIT();
    }

    const int ar  = (lane & 7) + ((lane >> 3) & 1) * 8;
    const int akl = (lane >> 4) & 1;
    const int br  = (lane & 7) + ((lane >> 4) & 1) * 8;
    const int bkl = (lane >> 3) & 1;

    int slot = 0;
    for (int s = 0; s < NSTAGE; s++) {
        if (s + 1 < NSTAGE) { CP_WAIT1(); } else { CP_WAIT0(); }
        __syncthreads();

        if (s + 2 < NSTAGE) {
            int koff = (s + 2) * 16;
            int ps = slot + 2; if (ps >= 3) ps -= 3;
            uint32_t dA = sdstA + ps * STAGE_BYTES;
            uint32_t dB = sdstB + ps * STAGE_BYTES;
            CP_ASYNC16(dB + OFF_BH, gBh + koff);
            CP_ASYNC16(dB + OFF_BL, gBl + koff);
            if (aload) {
                CP_ASYNC16(dA,          gAh + koff);
                CP_ASYNC16(dA + OFF_AL, gAl + koff);
            }
            CP_COMMIT();
        }

        const uint32_t s0 = sb + slot * STAGE_BYTES;

        uint32_t ahf[2][4], alf[2][4], bhf[4][2], blf[4][2];
        #pragma unroll
        for (int mt = 0; mt < 2; mt++) {
            int row = wm * 32 + mt * 16 + ar;
            uint32_t ad = s0 + row * SROW + ((akl ^ ((row >> 2) & 1)) * 16);
            LDSM4(ahf[mt], ad);
            LDSM4(alf[mt], ad + OFF_AL);
        }
        #pragma unroll
        for (int h = 0; h < 2; h++) {
            int row = wn * 32 + h * 16 + br;
            uint32_t bd = s0 + OFF_BH + row * SROW + ((bkl ^ ((row >> 2) & 1)) * 16);
            uint32_t r[4];
            LDSM4(r, bd);
            bhf[h * 2][0] = r[0]; bhf[h * 2][1] = r[1];
            bhf[h * 2 + 1][0] = r[2]; bhf[h * 2 + 1][1] = r[3];
            LDSM4(r, bd + (OFF_BL - OFF_BH));
            blf[h * 2][0] = r[0]; blf[h * 2][1] = r[1];
            blf[h * 2 + 1][0] = r[2]; blf[h * 2 + 1][1] = r[3];
        }

        #pragma unroll
        for (int mt = 0; mt < 2; mt++)
            #pragma unroll
            for (int nt = 0; nt < 4; nt++) {
                MMA16816(acc[mt][nt], ahf[mt], bhf[nt]);
                MMA16816(acc[mt][nt], alf[mt], bhf[nt]);
                MMA16816(acc[mt][nt], ahf[mt], blf[nt]);
            }

        if (++slot == 3) slot = 0;
    }

    if (EMODE == 4) {
        // ---- fused bias + row softmax (N == 128, bn == 0) ----
        #pragma unroll
        for (int mt = 0; mt < 2; mt++)
            #pragma unroll
            for (int half = 0; half < 2; half++)
                #pragma unroll
                for (int nt = 0; nt < 4; nt++) {
                    int c = wn * 32 + nt * 8 + (lane & 3) * 2;
                    acc[mt][nt][half * 2]     += obias[c];
                    acc[mt][nt][half * 2 + 1] += obias[c + 1];
                }
        float lm[2][2];
        #pragma unroll
        for (int mt = 0; mt < 2; mt++)
            #pragma unroll
            for (int half = 0; half < 2; half++) {
                float m = -3.4e38f;
                #pragma unroll
                for (int nt = 0; nt < 4; nt++) {
                    m = fmaxf(m, acc[mt][nt][half * 2]);
                    m = fmaxf(m, acc[mt][nt][half * 2 + 1]);
                }
                m = fmaxf(m, __shfl_xor_sync(0xFFFFFFFFu, m, 1));
                m = fmaxf(m, __shfl_xor_sync(0xFFFFFFFFu, m, 2));
                lm[mt][half] = m;
            }
        __syncthreads();
        if ((lane & 3) == 0) {
            #pragma unroll
            for (int mt = 0; mt < 2; mt++)
                #pragma unroll
                for (int half = 0; half < 2; half++) {
                    int rb = wm * 32 + mt * 16 + half * 8 + (lane >> 2);
                    rred[rb][wn] = lm[mt][half];
                }
        }
        __syncthreads();
        float Mrow[2][2];
        #pragma unroll
        for (int mt = 0; mt < 2; mt++)
            #pragma unroll
            for (int half = 0; half < 2; half++) {
                int rb = wm * 32 + mt * 16 + half * 8 + (lane >> 2);
                Mrow[mt][half] = fmaxf(fmaxf(rred[rb][0], rred[rb][1]),
                                       fmaxf(rred[rb][2], rred[rb][3]));
            }
        __syncthreads();
        float ls[2][2];
        #pragma unroll
        for (int mt = 0; mt < 2; mt++)
            #pragma unroll
            for (int half = 0; half < 2; half++) {
                float s = 0.f;
                #pragma unroll
                for (int nt = 0; nt < 4; nt++) {
                    float e0 = expf(acc[mt][nt][half * 2]     - Mrow[mt][half]);
                    float e1 = expf(acc[mt][nt][half * 2 + 1] - Mrow[mt][half]);
                    acc[mt][nt][half * 2]     = e0;
                    acc[mt][nt][half * 2 + 1] = e1;
                    s += e0 + e1;
                }
                s += __shfl_xor_sync(0xFFFFFFFFu, s, 1);
                s += __shfl_xor_sync(0xFFFFFFFFu, s, 2);
                ls[mt][half] = s;
            }
        if ((lane & 3) == 0) {
            #pragma unroll
            for (int mt = 0; mt < 2; mt++)
                #pragma unroll
                for (int half = 0; half < 2; half++) {
                    int rb = wm * 32 + mt * 16 + half * 8 + (lane >> 2);
                    rred[rb][wn] = ls[mt][half];
                }
        }
        __syncthreads();
        #pragma unroll
        for (int mt = 0; mt < 2; mt++)
            #pragma unroll
            for (int half = 0; half < 2; half++) {
                int rb = wm * 32 + mt * 16 + half * 8 + (lane >> 2);
                int r  = bm + rb;
                if (r >= M) continue;
                float inv = 1.0f / (rred[rb][0] + rred[rb][1] + rred[rb][2] + rred[rb][3]);
                #pragma unroll
                for (int nt = 0; nt < 4; nt++) {
                    int c = wn * 32 + nt * 8 + (lane & 3) * 2;
                    *reinterpret_cast<float2*>(&C[(size_t)r * N + c]) =
                        make_float2(acc[mt][nt][half * 2] * inv,
                                    acc[mt][nt][half * 2 + 1] * inv);
                }
            }
        return;
    }

    // ---- standard epilogues ----
    #pragma unroll
    for (int mt = 0; mt < 2; mt++) {
        int rbase = bm + wm * 32 + mt * 16 + (lane >> 2);
        #pragma unroll
        for (int half = 0; half < 2; half++) {
            int r = rbase + half * 8;
            if (r >= M) continue;
            float dv = (EMODE == 1) ? dinv[r] : 0.f;
            #pragma unroll
            for (int nt = 0; nt < 4; nt++) {
                int c = bn + wn * 32 + nt * 8 + (lane & 3) * 2;
                float x = acc[mt][nt][half * 2];
                float y = acc[mt][nt][half * 2 + 1];
                if (EMODE == 1) {
                    x *= dv; y *= dv;
                    *reinterpret_cast<float2*>(&C[(size_t)r * N + c]) = make_float2(x, y);
                } else if (EMODE == 2) {
                    x = fmaxf(x + obias[c], 0.f);
                    y = fmaxf(y + obias[c + 1], 0.f);
                    uint32_t hi, lo;
                    split_pair(x, y, hi, lo);
                    *reinterpret_cast<uint32_t*>(&Oh[(size_t)r * DF + c]) = hi;
                    *reinterpret_cast<uint32_t*>(&Ol[(size_t)r * DF + c]) = lo;
                }
            }
        }
    }
}

// ---------------------------------------------------------------------------
// kernel_launch — inputs: x, edge_index, W1, b1, W2, b2, Wf1, bf1, Wf2, bf2
// ---------------------------------------------------------------------------
extern "C" void kernel_launch(void* const* d_in, const int* in_sizes, int n_in,
                              void* d_out, int out_size)
{
    const float* x   = (const float*)d_in[0];
    const int*   ei  = (const int*)  d_in[1];
    const float* W1  = (const float*)d_in[2];
    const float* b1  = (const float*)d_in[3];
    const float* W2  = (const float*)d_in[4];
    const float* b2  = (const float*)d_in[5];
    const float* Wf1 = (const float*)d_in[6];
    const float* bf1 = (const float*)d_in[7];
    const float* Wf2 = (const float*)d_in[8];
    const float* bf2 = (const float*)d_in[9];

    const int NV = in_sizes[0] / DF;   // 20000
    const int E  = in_sizes[1] / 2;    // 320000
    const int* srcIdx = ei;
    const int* dstIdx = ei + E;

    float *bufA, *dinv;
    __nv_bfloat16 *ah, *al, *bh, *bl, *wh, *wl;
    int *cnt, *rowptr, *cursor, *col;
    cudaGetSymbolAddress((void**)&bufA, g_bufA);
    cudaGetSymbolAddress((void**)&dinv, g_dinv);
    cudaGetSymbolAddress((void**)&ah, g_ah);
    cudaGetSymbolAddress((void**)&al, g_al);
    cudaGetSymbolAddress((void**)&bh, g_bh);
    cudaGetSymbolAddress((void**)&bl, g_bl);
    cudaGetSymbolAddress((void**)&wh, g_wh);
    cudaGetSymbolAddress((void**)&wl, g_wl);
    cudaGetSymbolAddress((void**)&cnt, g_cnt);
    cudaGetSymbolAddress((void**)&rowptr, g_rowptr);
    cudaGetSymbolAddress((void**)&cursor, g_cursor);
    cudaGetSymbolAddress((void**)&col, g_col);

    const size_t W1o = 0, W2o = 512 * 512, Wf1o = 2 * 512 * 512, Wf2o = 3 * 512 * 512;

    const int nb  = (NV + 255) / 256;
    const int eb  = (E + 255) / 256;
    const int gwb = (NV * 32 + 255) / 256;
    const int spb = (NV * 128 + 255) / 256;
    const int wcb = (3 * 512 * 512 + 128 * 512 + 255) / 256;

    // CSR build (also produces dinv)
    zero_cnt   <<<nb, 256>>>(cnt, NV);
    hist_kernel<<<eb, 256>>>(cnt, dstIdx, E);
    scan_kernel<<<1, 256>>>(cnt, rowptr, cursor, dinv, NV);
    fill_kernel<<<eb, 256>>>(srcIdx, dstIdx, cursor, col, E);

    // merged weight convert (all 4 matrices)
    wconv_all<<<wcb, 256>>>(W1, W2, Wf1, Wf2, wh, wl);

    dim3 blk(256);
    dim3 g512(4, (NV + 63) / 64);
    dim3 g128(1, (NV + 63) / 64);

    // layer 1
    split0_kernel<<<spb, 256>>>(x, ah, al, NV);
    gemm_bf16x3<1><<<g512, blk>>>(ah, al, wh + W1o, wl + W1o,
                                  bufA, nullptr, nullptr, nullptr, dinv, NV, 512);
    gather_csr<<<gwb, 256>>>(bufA, rowptr, col, dinv, b1, ah, al, NV);

    // layer 2
    gemm_bf16x3<1><<<g512, blk>>>(ah, al, wh + W2o, wl + W2o,
                                  bufA, nullptr, nullptr, nullptr, dinv, NV, 512);
    gather_csr<<<gwb, 256>>>(bufA, rowptr, col, dinv, b2, ah, al, NV);

    // fc1
    gemm_bf16x3<2><<<g512, blk>>>(ah, al, wh + Wf1o, wl + Wf1o,
                                  nullptr, bh, bl, bf1, nullptr, NV, 512);

    // fc2 + fused softmax -> d_out
    gemm_bf16x3<4><<<g128, blk>>>(bh, bl, wh + Wf2o, wl + Wf2o,
                                  (float*)d_out, nullptr, nullptr, bf2, nullptr, NV, 128);
}